// round 10
// baseline (speedup 1.0000x reference)
#include <cuda_runtime.h>

// Problem constants
#define BB      2
#define NN      512
#define CC      64
#define HH      8
#define TN      64                   // rows per staged tile
#define NT      (NN / TN)            // 8 tiles
#define THREADS 512                  // 16 warps; each warp: 4 rows per tile
#define BUF_F4  (TN * 32)            // 2048 float4 per buffer
#define DYN_BYTES (2 * BUF_F4 * 16)  // 64 KB double buffer

typedef unsigned long long ull;

__device__ __forceinline__ ull pack2(float lo, float hi) {
    ull r; asm("mov.b64 %0, {%1, %2};" : "=l"(r) : "f"(lo), "f"(hi)); return r;
}
__device__ __forceinline__ ull fma2(ull a, ull b, ull c) {
    ull d; asm("fma.rn.f32x2 %0, %1, %2, %3;" : "=l"(d) : "l"(a), "l"(b), "l"(c)); return d;
}
__device__ __forceinline__ ull mul2(ull a, ull b) {
    ull d; asm("mul.rn.f32x2 %0, %1, %2;" : "=l"(d) : "l"(a), "l"(b)); return d;
}
__device__ __forceinline__ ull add2(ull a, ull b) {
    ull d; asm("add.rn.f32x2 %0, %1, %2;" : "=l"(d) : "l"(a), "l"(b)); return d;
}
__device__ __forceinline__ ull shfl64(ull v, int m) {
    return __shfl_xor_sync(0xffffffffu, v, m);
}
__device__ __forceinline__ void cpasync16(unsigned int dst, const void* src) {
    asm volatile("cp.async.cg.shared.global [%0], [%1], 16;" :: "r"(dst), "l"(src));
}

__global__ __launch_bounds__(THREADS, 2)
void mha_fused6(const float4* __restrict__ q4,
                const float4* __restrict__ k4,
                const float*  __restrict__ roi,
                const float4* __restrict__ W4,
                const float*  __restrict__ bias,
                float4*       __restrict__ out4)
{
    extern __shared__ float4 tile[];      // 2 x [TN][32] : q f4 0..15, k f4 16..31
    __shared__ float attn[NN * HH];       // 16 KB
    __shared__ float roism[NN];
    __shared__ float wsum[16 * HH];
    __shared__ float invs[HH];

    const int tid  = threadIdx.x;
    const int lane = tid & 31;
    const int warp = tid >> 5;
    const int row  = blockIdx.x;          // b*N + m

    const bool b0 = lane & 1, b1 = lane & 2, b2 = lane & 4;
    const bool b3 = lane & 8, b4 = lane & 16;
    // lane -> (head, local row) ownership after the blocked butterfly
    const int myhead = ((lane & 1) << 2) | (lane & 2) | ((lane >> 2) & 1);
    const int rho    = (b3 ? 1 : 0) + (b4 ? 2 : 0);

    // Lane-resident W, transposed into head-pairs: w{x,y,z,w}[j] = (comp of head 2j, head 2j+1)
    ull wx[4], wy[4], wz[4], wwr[4];
    #pragma unroll
    for (int j = 0; j < 4; ++j) {
        const float4 u = W4[(2 * j)     * 32 + lane];
        const float4 v = W4[(2 * j + 1) * 32 + lane];
        wx[j]  = pack2(u.x, v.x);
        wy[j]  = pack2(u.y, v.y);
        wz[j]  = pack2(u.z, v.z);
        wwr[j] = pack2(u.w, v.w);
    }
    const float breg = bias[myhead];

    roism[tid] = roi[(size_t)row * NN + tid];

    const float4* qg = q4 + (size_t)row * (NN * CC / 4);
    const float4* kg = k4 + (size_t)row * (NN * CC / 4);
    const unsigned int smem_base = (unsigned int)__cvta_generic_to_shared(tile);

    auto stage = [&](int t, int b) {
        const unsigned int dstb = smem_base + b * (BUF_F4 * 16);
        #pragma unroll
        for (int j = 0; j < 2; ++j) {
            const int idx = tid + j * 512;         // 0..1023 over 64x16 float4
            const int r = idx >> 4, c = idx & 15;
            cpasync16(dstb + (r * 32 + c) * 16,      qg + t * (TN * 16) + idx);
            cpasync16(dstb + (r * 32 + 16 + c) * 16, kg + t * (TN * 16) + idx);
        }
        asm volatile("cp.async.commit_group;" ::: "memory");
    };

    stage(0, 0);

    float psum = 0.f;

    #pragma unroll
    for (int t = 0; t < NT; ++t) {
        asm volatile("cp.async.wait_group 0;" ::: "memory");
        __syncthreads();                   // tile t visible; all warps done with t-1
        if (t < NT - 1) stage(t + 1, (t + 1) & 1);

        const float4* tb = tile + (t & 1) * BUF_F4;

        ull C[4];
        #pragma unroll
        for (int rr = 0; rr < 4; ++rr) {
            const int nl = warp * 4 + rr;
            const float4 a = tb[nl * 32 + lane];   // conflict-free per quarter-warp
            const ull xx = pack2(a.x, a.x);
            const ull yy = pack2(a.y, a.y);
            const ull zz = pack2(a.z, a.z);
            const ull ww = pack2(a.w, a.w);

            // packed partials: P[j] = (contrib to head 2j, head 2j+1)
            ull P0 = fma2(xx, wx[0], fma2(yy, wy[0], fma2(zz, wz[0], mul2(ww, wwr[0]))));
            ull P1 = fma2(xx, wx[1], fma2(yy, wy[1], fma2(zz, wz[1], mul2(ww, wwr[1]))));
            ull P2 = fma2(xx, wx[2], fma2(yy, wy[2], fma2(zz, wz[2], mul2(ww, wwr[2]))));
            ull P3 = fma2(xx, wx[3], fma2(yy, wy[3], fma2(zz, wz[3], mul2(ww, wwr[3]))));

            // blocked butterfly over lane bits 0,1 (distribute 4 pairs), then sum over bit 2
            ull Q0 = add2(b0 ? P2 : P0, shfl64(b0 ? P0 : P2, 1));
            ull Q1 = add2(b0 ? P3 : P1, shfl64(b0 ? P1 : P3, 1));
            ull R  = add2(b1 ? Q1 : Q0, shfl64(b1 ? Q0 : Q1, 2));
            R = add2(R, shfl64(R, 4));
            C[rr] = R;
        }

        // row-transposed tail over lane bits 3,4: 3 shfl64 for all 4 rows
        const ull A  = add2(b3 ? C[1] : C[0], shfl64(b3 ? C[0] : C[1], 8));
        const ull Bv = add2(b3 ? C[3] : C[2], shfl64(b3 ? C[2] : C[3], 8));
        const ull D  = add2(b4 ? Bv : A,      shfl64(b4 ? A : Bv, 16));

        float dlo, dhi;
        asm("mov.b64 {%0, %1}, %2;" : "=f"(dlo), "=f"(dhi) : "l"(D));
        const float logit = b2 ? dhi : dlo;   // lane now owns (row rho, head myhead)

        const int n = t * TN + warp * 4 + rho;
        const float val = __expf(logit + breg) * roism[n];
        psum += val;
        attn[n * HH + myhead] = val;          // 32 consecutive words: conflict-free
    }

    // ---- per-head sums: combine the 4 lanes sharing a head ----
    psum += __shfl_xor_sync(0xffffffffu, psum, 8);
    psum += __shfl_xor_sync(0xffffffffu, psum, 16);
    if (lane < 8) wsum[warp * HH + myhead] = psum;
    __syncthreads();
    if (tid < HH) {
        float s = 0.f;
        #pragma unroll
        for (int w = 0; w < 16; ++w) s += wsum[w * HH + tid];
        invs[tid] = 1.0f / s;
    }
    __syncthreads();

    // ---- coalesced normalize + store ----
    float4* ob = out4 + (size_t)row * (NN * HH / 4);
    const float4* at4 = (const float4*)attn;
    const float4* iv4 = (const float4*)invs;
    #pragma unroll
    for (int i = tid; i < NN * HH / 4; i += THREADS) {
        float4 a  = at4[i];
        float4 iv = iv4[i & 1];
        a.x *= iv.x; a.y *= iv.y; a.z *= iv.z; a.w *= iv.w;
        ob[i] = a;
    }
}

extern "C" void kernel_launch(void* const* d_in, const int* in_sizes, int n_in,
                              void* d_out, int out_size) {
    const float4* q   = (const float4*)d_in[0];
    const float4* k   = (const float4*)d_in[1];
    const float*  roi = (const float*)d_in[2];
    const float4* W   = (const float4*)d_in[3];
    const float*  b   = (const float*)d_in[4];
    float4* out = (float4*)d_out;

    cudaFuncSetAttribute(mha_fused6,
                         cudaFuncAttributeMaxDynamicSharedMemorySize, DYN_BYTES);
    mha_fused6<<<BB * NN, THREADS, DYN_BYTES>>>(q, k, roi, W, b, out);
}

// round 14
// speedup vs baseline: 1.2472x; 1.2472x over previous
#include <cuda_runtime.h>

// Problem constants
#define BB      2
#define NN      512
#define CC      64
#define HH      8
#define TN      64                   // rows per staged tile
#define NT      (NN / TN)            // 8 tiles
#define THREADS 512                  // 16 warps; each warp: 4 rows per tile
#define BUF_F4  (TN * 32)            // 2048 float4 per buffer
#define DYN_BYTES (2 * BUF_F4 * 16)  // 64 KB double buffer

typedef unsigned long long ull;

__device__ __forceinline__ ull pack2(float lo, float hi) {
    ull r; asm("mov.b64 %0, {%1, %2};" : "=l"(r) : "f"(lo), "f"(hi)); return r;
}
__device__ __forceinline__ ull fma2(ull a, ull b, ull c) {
    ull d; asm("fma.rn.f32x2 %0, %1, %2, %3;" : "=l"(d) : "l"(a), "l"(b), "l"(c)); return d;
}
__device__ __forceinline__ ull mul2(ull a, ull b) {
    ull d; asm("mul.rn.f32x2 %0, %1, %2;" : "=l"(d) : "l"(a), "l"(b)); return d;
}
__device__ __forceinline__ float unpadd(ull a) {
    float lo, hi; asm("mov.b64 {%0, %1}, %2;" : "=f"(lo), "=f"(hi) : "l"(a)); return lo + hi;
}
__device__ __forceinline__ float shf(float v, int m) {
    return __shfl_xor_sync(0xffffffffu, v, m);
}
__device__ __forceinline__ void cpasync16(unsigned int dst, const void* src) {
    asm volatile("cp.async.cg.shared.global [%0], [%1], 16;" :: "r"(dst), "l"(src));
}

__global__ __launch_bounds__(THREADS, 2)
void mha_fused7(const float4* __restrict__ q4,
                const float4* __restrict__ k4,
                const float*  __restrict__ roi,
                const float4* __restrict__ W4,
                const float*  __restrict__ bias,
                float4*       __restrict__ out4)
{
    extern __shared__ float4 tile[];      // 2 x [TN][32] : q f4 0..15, k f4 16..31
    __shared__ float attn[NN * HH];       // 16 KB
    __shared__ float roism[NN];
    __shared__ float wsum[16 * HH];
    __shared__ float invs[HH];

    const int tid  = threadIdx.x;
    const int lane = tid & 31;
    const int warp = tid >> 5;
    const int row  = blockIdx.x;          // b*N + m
    const int lh   = lane & 7;            // head this lane will own
    const int g    = (lane >> 3) & 3;     // row-in-group this lane will own

    // XOR-rotated lane-resident W: slot j holds head (j ^ lh).
    // This makes the butterfly below pure shfl+add with compile-time indices.
    ull wr[HH][2];
    #pragma unroll
    for (int j = 0; j < HH; ++j) {
        const float4 w = W4[(j ^ lh) * 32 + lane];
        wr[j][0] = pack2(w.x, w.y);
        wr[j][1] = pack2(w.z, w.w);
    }
    const float breg = bias[lh];

    roism[tid] = roi[(size_t)row * NN + tid];

    const float4* qg = q4 + (size_t)row * (NN * CC / 4);
    const float4* kg = k4 + (size_t)row * (NN * CC / 4);
    const unsigned int smem_base = (unsigned int)__cvta_generic_to_shared(tile);

    auto stage = [&](int t, int b) {
        const unsigned int dstb = smem_base + b * (BUF_F4 * 16);
        #pragma unroll
        for (int j = 0; j < 2; ++j) {
            const int idx = tid + j * 512;         // 0..1023 over 64x16 float4
            const int r = idx >> 4, c = idx & 15;
            cpasync16(dstb + (r * 32 + c) * 16,      qg + t * (TN * 16) + idx);
            cpasync16(dstb + (r * 32 + 16 + c) * 16, kg + t * (TN * 16) + idx);
        }
        asm volatile("cp.async.commit_group;" ::: "memory");
    };

    stage(0, 0);

    float psum = 0.f;

    #pragma unroll
    for (int t = 0; t < NT; ++t) {
        asm volatile("cp.async.wait_group 0;" ::: "memory");
        __syncthreads();                   // tile t visible; all warps done with t-1
        if (t < NT - 1) stage(t + 1, (t + 1) & 1);

        const float4* tb = tile + (t & 1) * BUF_F4;

        float rrow[4];
        #pragma unroll
        for (int rr = 0; rr < 4; ++rr) {
            const int nl = warp * 4 + rr;
            const float4 a = tb[nl * 32 + lane];   // conflict-free
            const ull a01 = pack2(a.x, a.y);
            const ull a23 = pack2(a.z, a.w);

            // v[j] = this lane's 4-component partial for head (j ^ lh)
            float v0 = unpadd(fma2(a01, wr[0][0], mul2(a23, wr[0][1])));
            float v1 = unpadd(fma2(a01, wr[1][0], mul2(a23, wr[1][1])));
            float v2 = unpadd(fma2(a01, wr[2][0], mul2(a23, wr[2][1])));
            float v3 = unpadd(fma2(a01, wr[3][0], mul2(a23, wr[3][1])));
            float v4 = unpadd(fma2(a01, wr[4][0], mul2(a23, wr[4][1])));
            float v5 = unpadd(fma2(a01, wr[5][0], mul2(a23, wr[5][1])));
            float v6 = unpadd(fma2(a01, wr[6][0], mul2(a23, wr[6][1])));
            float v7 = unpadd(fma2(a01, wr[7][0], mul2(a23, wr[7][1])));

            // SEL-free butterfly: after these, v0 = head lh partial over this octet
            v0 += shf(v1, 1);  v2 += shf(v3, 1);  v4 += shf(v5, 1);  v6 += shf(v7, 1);
            v0 += shf(v2, 2);  v4 += shf(v6, 2);
            v0 += shf(v4, 4);
            rrow[rr] = v0;
        }

        // Transposed tail: rotate rows by g, then 3 shfl complete the 4-octet sums
        // and land a distinct (row, head) on every lane.
        const bool gb0 = g & 1, gb1 = g & 2;
        const float s0 = gb0 ? rrow[1] : rrow[0];
        const float s1 = gb0 ? rrow[0] : rrow[1];
        const float s2 = gb0 ? rrow[3] : rrow[2];
        const float s3 = gb0 ? rrow[2] : rrow[3];
        float c0 = gb1 ? s2 : s0;
        float c1 = gb1 ? s3 : s1;
        float c2 = gb1 ? s0 : s2;
        float c3 = gb1 ? s1 : s3;
        c0 += shf(c1, 8);
        c2 += shf(c3, 8);
        c0 += shf(c2, 16);
        // c0 = logit(row warp*4+g, head lh), complete over all 128 components

        const int n = t * TN + warp * 4 + g;
        const float val = __expf(c0 + breg) * roism[n];
        psum += val;
        attn[n * HH + lh] = val;           // word index == base + lane: conflict-free
    }

    // ---- per-head sums: lanes sharing a head are L, L^8, L^16, L^24 (g=0..3) ----
    psum += shf(psum, 8);
    psum += shf(psum, 16);
    if (lane < 8) wsum[warp * HH + lane] = psum;   // lane<8 => lh==lane
    __syncthreads();
    if (tid < HH) {
        float s = 0.f;
        #pragma unroll
        for (int w = 0; w < 16; ++w) s += wsum[w * HH + tid];
        invs[tid] = 1.0f / s;
    }
    __syncthreads();

    // ---- coalesced normalize + store ----
    float4* ob = out4 + (size_t)row * (NN * HH / 4);
    const float4* at4 = (const float4*)attn;
    const float4* iv4 = (const float4*)invs;
    #pragma unroll
    for (int i = tid; i < NN * HH / 4; i += THREADS) {
        float4 a  = at4[i];
        float4 iv = iv4[i & 1];
        a.x *= iv.x; a.y *= iv.y; a.z *= iv.z; a.w *= iv.w;
        ob[i] = a;
    }
}

extern "C" void kernel_launch(void* const* d_in, const int* in_sizes, int n_in,
                              void* d_out, int out_size) {
    const float4* q   = (const float4*)d_in[0];
    const float4* k   = (const float4*)d_in[1];
    const float*  roi = (const float*)d_in[2];
    const float4* W   = (const float4*)d_in[3];
    const float*  b   = (const float*)d_in[4];
    float4* out = (float4*)d_out;

    cudaFuncSetAttribute(mha_fused7,
                         cudaFuncAttributeMaxDynamicSharedMemorySize, DYN_BYTES);
    mha_fused7<<<BB * NN, THREADS, DYN_BYTES>>>(q, k, roi, W, b, out);
}

// round 17
// speedup vs baseline: 1.3885x; 1.1133x over previous
#include <cuda_runtime.h>

// Problem constants
#define BB      2
#define NN      512
#define CC      64
#define HH      8
#define TN      64                   // rows per tile (4 per warp)
#define NT      (NN / TN)            // 8 tiles
#define THREADS 512                  // 16 warps
#define WBUF_F4 128                  // per-warp per-buffer float4 (4 rows x 32)
#define DYN_BYTES (2 * 16 * WBUF_F4 * 16)   // 64 KB (2 bufs x 16 warps x 2 KB)

typedef unsigned long long ull;

__device__ __forceinline__ ull pack2(float lo, float hi) {
    ull r; asm("mov.b64 %0, {%1, %2};" : "=l"(r) : "f"(lo), "f"(hi)); return r;
}
__device__ __forceinline__ ull fma2(ull a, ull b, ull c) {
    ull d; asm("fma.rn.f32x2 %0, %1, %2, %3;" : "=l"(d) : "l"(a), "l"(b), "l"(c)); return d;
}
__device__ __forceinline__ ull mul2(ull a, ull b) {
    ull d; asm("mul.rn.f32x2 %0, %1, %2;" : "=l"(d) : "l"(a), "l"(b)); return d;
}
__device__ __forceinline__ float unpadd(ull a) {
    float lo, hi; asm("mov.b64 {%0, %1}, %2;" : "=f"(lo), "=f"(hi) : "l"(a)); return lo + hi;
}
__device__ __forceinline__ float shf(float v, int m) {
    return __shfl_xor_sync(0xffffffffu, v, m);
}
__device__ __forceinline__ void cpasync16(unsigned int dst, const void* src) {
    asm volatile("cp.async.cg.shared.global [%0], [%1], 16;" :: "r"(dst), "l"(src));
}

__global__ __launch_bounds__(THREADS, 2)
void mha_fused8(const float4* __restrict__ q4,
                const float4* __restrict__ k4,
                const float*  __restrict__ roi,
                const float4* __restrict__ W4,
                const float*  __restrict__ bias,
                float4*       __restrict__ out4)
{
    extern __shared__ float4 tile[];      // [2][16 warps][4 rows][32 f4]
    __shared__ float attn[NN * HH];       // 16 KB
    __shared__ float roism[NN];
    __shared__ float wsum[16 * HH];
    __shared__ float invs[HH];

    const int tid  = threadIdx.x;
    const int lane = tid & 31;
    const int warp = tid >> 5;
    const int row  = blockIdx.x;          // b*N + m
    const int lh   = lane & 7;            // head this lane will own
    const int g    = (lane >> 3) & 3;     // row-in-group this lane will own

    // XOR-rotated lane-resident W: slot j holds head (j ^ lh) -> SEL-free butterfly.
    ull wr[HH][2];
    #pragma unroll
    for (int j = 0; j < HH; ++j) {
        const float4 w = W4[(j ^ lh) * 32 + lane];
        wr[j][0] = pack2(w.x, w.y);
        wr[j][1] = pack2(w.z, w.w);
    }
    const float breg = bias[lh];

    roism[tid] = roi[(size_t)row * NN + tid];

    // Per-lane staging source: lanes 0-15 carry q float4s, 16-31 carry k float4s.
    const float4* gbase = ((lane < 16) ? q4 : k4) + (size_t)row * (NN * CC / 4) + (lane & 15);
    const unsigned int smem_base = (unsigned int)__cvta_generic_to_shared(tile);
    const unsigned int wbase = smem_base + warp * (WBUF_F4 * 16);   // this warp's buf0

    // --- per-warp async stage of its own 4 rows of tile t into buffer b ---
    auto stageW = [&](int t, int b) {
        const unsigned int dstb = wbase + b * (16 * WBUF_F4 * 16) + lane * 16;
        const float4* src = gbase + (size_t)(t * TN + warp * 4) * 16;
        #pragma unroll
        for (int rr = 0; rr < 4; ++rr)
            cpasync16(dstb + rr * 512, src + rr * 16);
        asm volatile("cp.async.commit_group;" ::: "memory");
    };

    stageW(0, 0);
    stageW(1, 1);
    __syncthreads();                      // roism visibility only

    float psum = 0.f;

    #pragma unroll
    for (int t = 0; t < NT; ++t) {
        if (t < NT - 1) asm volatile("cp.async.wait_group 1;" ::: "memory");
        else            asm volatile("cp.async.wait_group 0;" ::: "memory");

        const float4* tb = tile + ((t & 1) * 16 + warp) * WBUF_F4;

        float rrow[4];
        #pragma unroll
        for (int rr = 0; rr < 4; ++rr) {
            const float4 a = tb[rr * 32 + lane];     // conflict-free
            const ull a01 = pack2(a.x, a.y);
            const ull a23 = pack2(a.z, a.w);

            float v0 = unpadd(fma2(a01, wr[0][0], mul2(a23, wr[0][1])));
            float v1 = unpadd(fma2(a01, wr[1][0], mul2(a23, wr[1][1])));
            float v2 = unpadd(fma2(a01, wr[2][0], mul2(a23, wr[2][1])));
            float v3 = unpadd(fma2(a01, wr[3][0], mul2(a23, wr[3][1])));
            float v4 = unpadd(fma2(a01, wr[4][0], mul2(a23, wr[4][1])));
            float v5 = unpadd(fma2(a01, wr[5][0], mul2(a23, wr[5][1])));
            float v6 = unpadd(fma2(a01, wr[6][0], mul2(a23, wr[6][1])));
            float v7 = unpadd(fma2(a01, wr[7][0], mul2(a23, wr[7][1])));

            // SEL-free butterfly: v0 = head (lane&7) partial over this octet
            v0 += shf(v1, 1);  v2 += shf(v3, 1);  v4 += shf(v5, 1);  v6 += shf(v7, 1);
            v0 += shf(v2, 2);  v4 += shf(v6, 2);
            v0 += shf(v4, 4);
            rrow[rr] = v0;
        }

        // consumed buffer (t&1) -> restage it with tile t+2 (warp-local, no barrier)
        if (t < NT - 2) stageW(t + 2, t & 1);

        // Transposed tail: rotate rows by g, 3 shfl finish the 4-octet sums,
        // landing a distinct (row, head) on every lane.
        const bool gb0 = g & 1, gb1 = g & 2;
        const float s0 = gb0 ? rrow[1] : rrow[0];
        const float s1 = gb0 ? rrow[0] : rrow[1];
        const float s2 = gb0 ? rrow[3] : rrow[2];
        const float s3 = gb0 ? rrow[2] : rrow[3];
        float c0 = gb1 ? s2 : s0;
        float c1 = gb1 ? s3 : s1;
        float c2 = gb1 ? s0 : s2;
        float c3 = gb1 ? s1 : s3;
        c0 += shf(c1, 8);
        c2 += shf(c3, 8);
        c0 += shf(c2, 16);
        // c0 = logit(row warp*4+g, head lane&7)

        const int n = t * TN + warp * 4 + g;
        const float val = __expf(c0 + breg) * roism[n];
        psum += val;
        attn[n * HH + lh] = val;           // 32 consecutive words: conflict-free
    }

    // ---- per-head sums ----
    psum += shf(psum, 8);
    psum += shf(psum, 16);
    if (lane < 8) wsum[warp * HH + lane] = psum;
    __syncthreads();
    if (tid < HH) {
        float s = 0.f;
        #pragma unroll
        for (int w = 0; w < 16; ++w) s += wsum[w * HH + tid];
        invs[tid] = 1.0f / s;
    }
    __syncthreads();

    // ---- coalesced normalize + store ----
    float4* ob = out4 + (size_t)row * (NN * HH / 4);
    const float4* at4 = (const float4*)attn;
    const float4* iv4 = (const float4*)invs;
    #pragma unroll
    for (int i = tid; i < NN * HH / 4; i += THREADS) {
        float4 a  = at4[i];
        float4 iv = iv4[i & 1];
        a.x *= iv.x; a.y *= iv.y; a.z *= iv.z; a.w *= iv.w;
        ob[i] = a;
    }
}

extern "C" void kernel_launch(void* const* d_in, const int* in_sizes, int n_in,
                              void* d_out, int out_size) {
    const float4* q   = (const float4*)d_in[0];
    const float4* k   = (const float4*)d_in[1];
    const float*  roi = (const float*)d_in[2];
    const float4* W   = (const float4*)d_in[3];
    const float*  b   = (const float*)d_in[4];
    float4* out = (float4*)d_out;

    cudaFuncSetAttribute(mha_fused8,
                         cudaFuncAttributeMaxDynamicSharedMemorySize, DYN_BYTES);
    mha_fused8<<<BB * NN, THREADS, DYN_BYTES>>>(q, k, roi, W, b, out);
}